// round 15
// baseline (speedup 1.0000x reference)
#include <cuda_runtime.h>
#include <cuda_fp16.h>
#include <cuda_bf16.h>
#include <math.h>

#define NTOK 4096
#define QSCALE 0.2550760660737454f   /* (1/sqrt(32)) * log2(e) */
#define NEGL2  -1e30f
#define PLANEB 524288                /* bytes per head-pair fp16 plane: 4096*64*2 */
#define AQP 524288                   /* bytes per K-quarter plane of x/att: 4096*64*2 */
#define WQP 131072                   /* bytes per K-quarter plane of W: 1024*64*2 */

// ---- device scratch (allocation-free rule) ----
// x/att/W bf16 arrays: FOUR K-quarter planes; rows are 128B (64 cols),
// chunk-xor swizzled (chunk ^= row&7) for conflict-free ldmatrix.
static __device__ __align__(1024) __nv_bfloat16 g_xh[NTOK * 256], g_xl[NTOK * 256];
static __device__ __align__(1024) __nv_bfloat16 g_ath[NTOK * 256], g_atl[NTOK * 256];
static __device__ __align__(1024) __nv_bfloat16 g_wth[1024 * 256], g_wtl[1024 * 256];
static __device__ __align__(1024) __half g_q16[NTOK * 256];
static __device__ __align__(1024) __half g_k16[NTOK * 256];
static __device__ __align__(1024) __half g_v16[NTOK * 256];
static __device__ __align__(1024) unsigned g_amask[128 * NTOK];   // [tile32][q]

// ---------------- helpers ----------------
#define PKH(d, lo, hi) \
    asm("cvt.rn.f16x2.f32 %0, %1, %2;" : "=r"(d) : "f"(hi), "f"(lo))
#define PKBF(d, lo, hi) \
    asm("cvt.rn.bf16x2.f32 %0, %1, %2;" : "=r"(d) : "f"(hi), "f"(lo))
#define EX2H2(d, a) \
    asm("ex2.approx.f16x2 %0, %1;" : "=r"(d) : "r"(a))

__device__ __forceinline__ void ldsm4(uint4& r, unsigned addr) {
    asm volatile("ldmatrix.sync.aligned.m8n8.x4.shared.b16 {%0,%1,%2,%3}, [%4];"
                 : "=r"(r.x), "=r"(r.y), "=r"(r.z), "=r"(r.w) : "r"(addr));
}
__device__ __forceinline__ void ldsm4t(uint4& r, unsigned addr) {
    asm volatile("ldmatrix.sync.aligned.m8n8.x4.trans.shared.b16 {%0,%1,%2,%3}, [%4];"
                 : "=r"(r.x), "=r"(r.y), "=r"(r.z), "=r"(r.w) : "r"(addr));
}
__device__ __forceinline__ void mma_f16(
    float& d0, float& d1, float& d2, float& d3,
    unsigned a0, unsigned a1, unsigned a2, unsigned a3,
    unsigned b0, unsigned b1)
{
    asm("mma.sync.aligned.m16n8k16.row.col.f32.f16.f16.f32 "
        "{%0,%1,%2,%3},{%4,%5,%6,%7},{%8,%9},{%0,%1,%2,%3};"
        : "+f"(d0), "+f"(d1), "+f"(d2), "+f"(d3)
        : "r"(a0), "r"(a1), "r"(a2), "r"(a3), "r"(b0), "r"(b1));
}
__device__ __forceinline__ void mma_bf16(
    float& d0, float& d1, float& d2, float& d3,
    unsigned a0, unsigned a1, unsigned a2, unsigned a3,
    unsigned b0, unsigned b1)
{
    asm("mma.sync.aligned.m16n8k16.row.col.f32.bf16.bf16.f32 "
        "{%0,%1,%2,%3},{%4,%5,%6,%7},{%8,%9},{%0,%1,%2,%3};"
        : "+f"(d0), "+f"(d1), "+f"(d2), "+f"(d3)
        : "r"(a0), "r"(a1), "r"(a2), "r"(a3), "r"(b0), "r"(b1));
}
__device__ __forceinline__ void mbar_init(unsigned addr, unsigned cnt) {
    asm volatile("mbarrier.init.shared.b64 [%0], %1;" :: "r"(addr), "r"(cnt) : "memory");
}
__device__ __forceinline__ void mbar_expect(unsigned addr, unsigned tx) {
    asm volatile("mbarrier.arrive.expect_tx.shared.b64 _, [%0], %1;"
                 :: "r"(addr), "r"(tx) : "memory");
}
__device__ __forceinline__ void mbar_wait(unsigned addr, unsigned phase) {
    unsigned done = 0;
    while (!done) {
        asm volatile(
            "{\n .reg .pred p;\n"
            " mbarrier.try_wait.parity.acquire.cta.shared::cta.b64 p, [%1], %2, 0x989680;\n"
            " selp.b32 %0, 1, 0, p;\n}"
            : "=r"(done) : "r"(addr), "r"(phase) : "memory");
    }
}
__device__ __forceinline__ void bulkcp(unsigned dst, const void* src,
                                       unsigned bytes, unsigned mbar) {
    unsigned long long ga;
    asm("cvta.to.global.u64 %0, %1;" : "=l"(ga) : "l"(src));
    asm volatile(
        "cp.async.bulk.shared::cta.global.mbarrier::complete_tx::bytes "
        "[%0], [%1], %2, [%3];"
        :: "r"(dst), "l"(ga), "r"(bytes), "r"(mbar) : "memory");
}

// 128-byte rows (64 x 2B cols), chunk-xor swizzle
__device__ __forceinline__ unsigned swzP(int row, int c) {
    return (unsigned)(row * 128 + ((((c >> 3) ^ (row & 7))) << 4)
                      + ((c & 7) << 1));
}

// ---------------------------------------------------------------------------
// prep: blockIdx < 1024  -> x fp32 -> hi/lo bf16 K-quarter planes
//       1024..1279       -> W transpose -> hi/lo bf16 K-quarter planes
//       1280..1791       -> adj -> bitmask (warp-per-row, coalesced)
// ---------------------------------------------------------------------------
__global__ __launch_bounds__(256) void prep_kernel(
    const float* __restrict__ x, const float* __restrict__ adj,
    const float* __restrict__ Wq, const float* __restrict__ Wk,
    const float* __restrict__ Wv, const float* __restrict__ Wo)
{
    const unsigned b = blockIdx.x;
    if (b < 1024) {
        int idx = b * 256 + threadIdx.x;
        int row = idx >> 6;
        int c4 = (idx & 63) << 2;
        float4 v = *(const float4*)&x[row * 256 + c4];
        unsigned h0, h1, l0, l1;
        PKBF(h0, v.x, v.y);
        PKBF(h1, v.z, v.w);
        float r0 = v.x - __uint_as_float(h0 << 16);
        float r1 = v.y - __uint_as_float(h0 & 0xffff0000u);
        float r2 = v.z - __uint_as_float(h1 << 16);
        float r3 = v.w - __uint_as_float(h1 & 0xffff0000u);
        PKBF(l0, r0, r1);
        PKBF(l1, r2, r3);
        unsigned off = (unsigned)(c4 >> 6) * AQP + swzP(row, c4 & 63);
        uint2 hw = {h0, h1}, lw = {l0, l1};
        *(uint2*)((char*)g_xh + off) = hw;
        *(uint2*)((char*)g_xl + off) = lw;
        return;
    }
    if (b >= 1280) {
        const int q = ((b - 1280) << 3) + (threadIdx.x >> 5);
        const int lane = threadIdx.x & 31;
        const float* row = adj + (size_t)q * NTOK + lane;
#pragma unroll 4
        for (int t = 0; t < 128; t++) {
            float v = row[t << 5];
            unsigned wmask = __ballot_sync(0xffffffffu, v > 0.f);
            if (lane == 0) g_amask[t * NTOK + q] = wmask;
        }
        return;
    }
    __shared__ float sm[32][33];
    const int wb = b - 1024;                    // 0..255
    const int tx = threadIdx.x & 31, ty = threadIdx.x >> 5;
    const int kb = (wb & 7) * 32;
    const int nbi = wb >> 3;
    const int plane = nbi >> 3;
    const float* W = plane == 0 ? Wq : plane == 1 ? Wk : plane == 2 ? Wv : Wo;
    const int nloc = (nbi & 7) * 32;
#pragma unroll
    for (int i = 0; i < 4; i++) {
        int kr = ty * 4 + i;
        sm[kr][tx] = W[(kb + kr) * 256 + nloc + tx];
    }
    __syncthreads();
#pragma unroll
    for (int i = 0; i < 4; i++) {
        int nr = ty * 4 + i;
        float v = sm[tx][nr];
        __nv_bfloat16 h = __float2bfloat16_rn(v);
        __nv_bfloat16 l = __float2bfloat16_rn(v - __bfloat162float(h));
        int grow = plane * 256 + nloc + nr;
        int col = kb + tx;
        unsigned off = (unsigned)(col >> 6) * WQP + swzP(grow, col & 63);
        *(__nv_bfloat16*)((char*)g_wth + off) = h;
        *(__nv_bfloat16*)((char*)g_wtl + off) = l;
    }
}

// ---------------------------------------------------------------------------
// Tensor-core GEMM, M=64 N=64 tiles, K in 4 quarter-stages of 32KB (2 buffered).
// grid (64, NT); 2 CTAs/SM. (unchanged from round 14)
// ---------------------------------------------------------------------------
#define QSTG 32768
#define QA_H 0
#define QA_L 8192
#define QW_H 16384
#define QW_L 24576
#define PBAR 65536
#define GSMEM 65568

template <int MODE>
__global__ __launch_bounds__(256, 2) void gemm_tc_kernel(
    const float* __restrict__ bias0, const float* __restrict__ bias1,
    const float* __restrict__ bias2, float* __restrict__ C)
{
    extern __shared__ char smc[];
    unsigned sb = (unsigned)__cvta_generic_to_shared(smc);

    const int wrow0 = MODE == 0 ? 0 : 768;

    const int tid = threadIdx.x;
    const int lane = tid & 31;
    const int w = tid >> 5;
    const int wm = (w & 3) << 4;
    const int wn = (w >> 2) << 5;
    const int mb = blockIdx.x * 64;
    const int nb = blockIdx.y * 64;
    const int g = lane >> 2, tig = lane & 3;
    const int l7 = lane & 7, lb3 = (lane >> 3) & 1, lb4 = lane >> 4;

    const char* ah = MODE == 0 ? (const char*)g_xh : (const char*)g_ath;
    const char* al = MODE == 0 ? (const char*)g_xl : (const char*)g_atl;
    const int wrow = wrow0 + nb;

    if (tid == 0) {
        mbar_init(sb + PBAR, 1);
        mbar_init(sb + PBAR + 8, 1);
        asm volatile("fence.proxy.async.shared::cta;" ::: "memory");
    }
    __syncthreads();
    if (tid == 0) {
#pragma unroll
        for (int q = 0; q < 2; q++) {
            unsigned bar = sb + PBAR + q * 8;
            unsigned base = sb + q * QSTG;
            mbar_expect(bar, QSTG);
            bulkcp(base + QA_H, ah + (size_t)q * AQP + (size_t)mb * 128, 8192, bar);
            bulkcp(base + QA_L, al + (size_t)q * AQP + (size_t)mb * 128, 8192, bar);
            bulkcp(base + QW_H, (const char*)g_wth + (size_t)q * WQP
                   + (size_t)wrow * 128, 8192, bar);
            bulkcp(base + QW_L, (const char*)g_wtl + (size_t)q * WQP
                   + (size_t)wrow * 128, 8192, bar);
        }
    }

    float acc[4][4];
#pragma unroll
    for (int i = 0; i < 4; i++)
#pragma unroll
        for (int j = 0; j < 4; j++) acc[i][j] = 0.f;

    for (int q = 0; q < 4; q++) {
        const int cur = q & 1;
        mbar_wait(sb + PBAR + cur * 8, (q >> 1) & 1);
        const unsigned base = sb + cur * QSTG;
#pragma unroll
        for (int kc = 0; kc < 4; kc++) {
            uint4 ahf, alf;
            {
                unsigned off = swzP(wm + (lane & 15),
                                    kc * 16 + ((lane >> 4) << 3));
                ldsm4(ahf, base + QA_H + off);
                ldsm4(alf, base + QA_L + off);
            }
            uint4 wh[2], wl[2];
#pragma unroll
            for (int p = 0; p < 2; p++) {
                unsigned off = swzP(wn + 16 * p + lb4 * 8 + l7, kc * 16 + lb3 * 8);
                ldsm4(wh[p], base + QW_H + off);
                ldsm4(wl[p], base + QW_L + off);
            }
#pragma unroll
            for (int nf = 0; nf < 4; nf++) {
                const int p = nf >> 1, s = nf & 1;
                unsigned bh0 = s ? wh[p].z : wh[p].x;
                unsigned bh1 = s ? wh[p].w : wh[p].y;
                unsigned bl0 = s ? wl[p].z : wl[p].x;
                unsigned bl1 = s ? wl[p].w : wl[p].y;
                float* a = acc[nf];
                mma_bf16(a[0], a[1], a[2], a[3],
                         ahf.x, ahf.y, ahf.z, ahf.w, bh0, bh1);
                mma_bf16(a[0], a[1], a[2], a[3],
                         alf.x, alf.y, alf.z, alf.w, bh0, bh1);
                mma_bf16(a[0], a[1], a[2], a[3],
                         ahf.x, ahf.y, ahf.z, ahf.w, bl0, bl1);
            }
        }
        __syncthreads();
        if (tid == 0 && q < 2) {
            const int nq = q + 2;
            unsigned bar = sb + PBAR + cur * 8;
            unsigned bs = sb + cur * QSTG;
            mbar_expect(bar, QSTG);
            bulkcp(bs + QA_H, ah + (size_t)nq * AQP + (size_t)mb * 128, 8192, bar);
            bulkcp(bs + QA_L, al + (size_t)nq * AQP + (size_t)mb * 128, 8192, bar);
            bulkcp(bs + QW_H, (const char*)g_wth + (size_t)nq * WQP
                   + (size_t)wrow * 128, 8192, bar);
            bulkcp(bs + QW_L, (const char*)g_wtl + (size_t)nq * WQP
                   + (size_t)wrow * 128, 8192, bar);
        }
    }

    const int r0 = mb + wm + g;
    if (MODE == 0) {
        const int nwarp = nb + wn;
        const int plane = nwarp >> 8;
        const float* bias = plane == 0 ? bias0 : plane == 1 ? bias1 : bias2;
        __half* dst = plane == 0 ? g_q16 : plane == 1 ? g_k16 : g_v16;
        const float scale = plane == 0 ? QSCALE : 1.0f;
#pragma unroll
        for (int nf = 0; nf < 4; nf++) {
            int c = (nwarp & 255) + tig * 2 + nf * 8;
            float b0 = bias[c], b1 = bias[c + 1];
            float v00 = (acc[nf][0] + b0) * scale;
            float v01 = (acc[nf][1] + b1) * scale;
            float v10 = (acc[nf][2] + b0) * scale;
            float v11 = (acc[nf][3] + b1) * scale;
            unsigned p0, p1;
            PKH(p0, v00, v01);
            PKH(p1, v10, v11);
            size_t pb = (size_t)(c >> 6) * PLANEB;
            *(unsigned*)((char*)dst + pb + swzP(r0, c & 63)) = p0;
            *(unsigned*)((char*)dst + pb + swzP(r0 + 8, c & 63)) = p1;
        }
    } else {
#pragma unroll
        for (int nf = 0; nf < 4; nf++) {
            int c = nb + wn + tig * 2 + nf * 8;
            float b0 = bias0[c], b1 = bias0[c + 1];
            float2 o0 = {acc[nf][0] + b0, acc[nf][1] + b1};
            float2 o1 = {acc[nf][2] + b0, acc[nf][3] + b1};
            *(float2*)&C[(size_t)r0 * 256 + c] = o0;
            *(float2*)&C[(size_t)(r0 + 8) * 256 + c] = o1;
        }
    }
}

// ---------------------------------------------------------------------------
// fp16 flash attention, head-pair planes, 32-key tiles, 4-deep KV ring.
// grid 256 = 64 q-tiles x 4 planes; block 256 thr / 8 warps, 2 CTAs/SM.
// Mask applied as bitwise AND on f16x2 P after ex2 (exact same semantics).
// ---------------------------------------------------------------------------
#define AQ_OFF 0
#define AT_OFF 8192
#define ABUF 8192
#define ABAR 40960                  /* full0..full3, qbar */
#define ASMEM 41008

__device__ __forceinline__ void stage_kv(unsigned sb, int t,
                                         size_t plane_off) {
    const int buf = t & 3;
    unsigned bar = sb + ABAR + buf * 8;
    unsigned base = sb + AT_OFF + buf * ABUF;
    size_t go = plane_off + (size_t)t * 4096;
    mbar_expect(bar, 8192);
    bulkcp(base,        (const char*)g_k16 + go, 4096, bar);
    bulkcp(base + 4096, (const char*)g_v16 + go, 4096, bar);
}

__global__ __launch_bounds__(256, 2) void attn_kernel()
{
    extern __shared__ char smc[];
    unsigned sb = (unsigned)__cvta_generic_to_shared(smc);

    const int tid = threadIdx.x;
    const int lane = tid & 31;
    const int w = tid >> 5;
    const int hw = w & 1;
    const int qs = (w >> 1) << 4;
    const int hcb = hw << 5;
    const int qtile = blockIdx.x & 63;
    const int hp = blockIdx.x >> 6;
    const int qb = qtile << 6;
    const size_t plane_off = (size_t)hp * PLANEB;
    const int g = lane >> 2, tig = lane & 3;
    const int l7 = lane & 7, lb3 = (lane >> 3) & 1, lb4 = lane >> 4;

    if (tid == 0) {
        mbar_init(sb + ABAR, 1);
        mbar_init(sb + ABAR + 8, 1);
        mbar_init(sb + ABAR + 16, 1);
        mbar_init(sb + ABAR + 24, 1);
        mbar_init(sb + ABAR + 32, 1);   // q
        asm volatile("fence.proxy.async.shared::cta;" ::: "memory");
    }
    __syncthreads();
    if (tid == 0) {
        unsigned qbar = sb + ABAR + 32;
        mbar_expect(qbar, 8192);
        bulkcp(sb + AQ_OFF, (const char*)g_q16 + plane_off + (size_t)qb * 128,
               8192, qbar);
        stage_kv(sb, 0, plane_off);
        stage_kv(sb, 1, plane_off);
        stage_kv(sb, 2, plane_off);
    }

    const unsigned* am = g_amask + qb + qs + g;
    unsigned mw0 = __ldg(am) >> (2 * tig);
    unsigned mw1 = __ldg(am + 8) >> (2 * tig);

    mbar_wait(sb + ABAR + 32, 0);

    unsigned qf[2][4];
#pragma unroll
    for (int kc = 0; kc < 2; kc++) {
        unsigned off = swzP(qs + (lane & 15), hcb + kc * 16 + ((lane >> 4) << 3));
        uint4 r;
        ldsm4(r, sb + AQ_OFF + off);
        qf[kc][0] = r.x; qf[kc][1] = r.y; qf[kc][2] = r.z; qf[kc][3] = r.w;
    }

    float oc[4][4];
#pragma unroll
    for (int i = 0; i < 4; i++)
#pragma unroll
        for (int j = 0; j < 4; j++) oc[i][j] = 0.f;
    float l0 = 0.f, l1 = 0.f;

    for (int t = 0; t < 128; t++) {
        // stage 3 tiles ahead (buffer released by previous iteration's sync)
        if (tid == 0 && t + 3 < 128) stage_kv(sb, t + 3, plane_off);

        unsigned nw0 = 0, nw1 = 0;
        if (t < 127) {
            nw0 = __ldg(am + (t + 1) * NTOK) >> (2 * tig);
            nw1 = __ldg(am + (t + 1) * NTOK + 8) >> (2 * tig);
        }
        mbar_wait(sb + ABAR + (t & 3) * 8, (t >> 2) & 1);
        const unsigned tb = sb + AT_OFF + (t & 3) * ABUF;

        uint4 kf[2][2];
#pragma unroll
        for (int kc = 0; kc < 2; kc++)
#pragma unroll
            for (int p = 0; p < 2; p++)
                ldsm4(kf[kc][p], tb + swzP(16 * p + lb4 * 8 + l7,
                                           hcb + kc * 16 + lb3 * 8));

        float sc[4][4];
#pragma unroll
        for (int i = 0; i < 4; i++)
#pragma unroll
            for (int j = 0; j < 4; j++) sc[i][j] = 0.f;
#pragma unroll
        for (int nt = 0; nt < 4; nt++) {
            const int p = nt >> 1, s = nt & 1;
#pragma unroll
            for (int kc = 0; kc < 2; kc++) {
                unsigned b0 = s ? kf[kc][p].z : kf[kc][p].x;
                unsigned b1 = s ? kf[kc][p].w : kf[kc][p].y;
                mma_f16(sc[nt][0], sc[nt][1], sc[nt][2], sc[nt][3],
                        qf[kc][0], qf[kc][1], qf[kc][2], qf[kc][3], b0, b1);
            }
        }

        // ---- exp (fixed shift) then bitwise mask; l accumulation ----
        unsigned pA[4][2];
        __half2 lh0 = __float2half2_rn(0.f), lh1 = __float2half2_rn(0.f);
#pragma unroll
        for (int nt = 0; nt < 4; nt++) {
            unsigned b0 = (mw0 >> (nt * 8)) & 3;
            unsigned b1 = (mw1 >> (nt * 8)) & 3;
            unsigned m0 = ((b0 & 1) ? 0x0000FFFFu : 0u) | ((b0 & 2) ? 0xFFFF0000u : 0u);
            unsigned m1 = ((b1 & 1) ? 0x0000FFFFu : 0u) | ((b1 & 2) ? 0xFFFF0000u : 0u);
            unsigned h0, h1;
            PKH(h0, sc[nt][0], sc[nt][1]);
            PKH(h1, sc[nt][2], sc[nt][3]);
            EX2H2(pA[nt][0], h0);
            EX2H2(pA[nt][1], h1);
            pA[nt][0] &= m0;
            pA[nt][1] &= m1;
            lh0 = __hadd2(lh0, *(__half2*)&pA[nt][0]);
            lh1 = __hadd2(lh1, *(__half2*)&pA[nt][1]);
        }
        {
            float2 f0 = __half22float2(lh0);
            float2 f1 = __half22float2(lh1);
            l0 += f0.x + f0.y;
            l1 += f1.x + f1.y;
        }

        uint4 vf[2][2];
#pragma unroll
        for (int kc = 0; kc < 2; kc++)
#pragma unroll
            for (int p = 0; p < 2; p++)
                ldsm4t(vf[kc][p], tb + 4096 + swzP(kc * 16 + lb3 * 8 + l7,
                                                   hcb + p * 16 + lb4 * 8));

#pragma unroll
        for (int nt = 0; nt < 4; nt++) {
            const int p = nt >> 1, s = nt & 1;
#pragma unroll
            for (int kc = 0; kc < 2; kc++) {
                unsigned b0 = s ? vf[kc][p].z : vf[kc][p].x;
                unsigned b1 = s ? vf[kc][p].w : vf[kc][p].y;
                mma_f16(oc[nt][0], oc[nt][1], oc[nt][2], oc[nt][3],
                        pA[2 * kc][0], pA[2 * kc][1],
                        pA[2 * kc + 1][0], pA[2 * kc + 1][1], b0, b1);
            }
        }

        __syncthreads();
        mw0 = nw0; mw1 = nw1;
    }

    l0 += __shfl_xor_sync(0xffffffffu, l0, 1);
    l0 += __shfl_xor_sync(0xffffffffu, l0, 2);
    l1 += __shfl_xor_sync(0xffffffffu, l1, 1);
    l1 += __shfl_xor_sync(0xffffffffu, l1, 2);
    float inv0 = 1.f / l0, inv1 = 1.f / l1;

    // epilogue -> hi/lo bf16 in K-quarter-plane layout for the output gemm
    const int r0 = qb + qs + g;
    const int colb = ((hp << 1) + hw) * 32 + tig * 2;
#pragma unroll
    for (int nt = 0; nt < 4; nt++) {
        int c = colb + nt * 8;
        float v00 = oc[nt][0] * inv0, v01 = oc[nt][1] * inv0;
        float v10 = oc[nt][2] * inv1, v11 = oc[nt][3] * inv1;
        unsigned h0, h1, lo0, lo1;
        PKBF(h0, v00, v01);
        PKBF(h1, v10, v11);
        float e0 = v00 - __uint_as_float(h0 << 16);
        float e1 = v01 - __uint_as_float(h0 & 0xffff0000u);
        float e2 = v10 - __uint_as_float(h1 << 16);
        float e3 = v11 - __uint_as_float(h1 & 0xffff0000u);
        PKBF(lo0, e0, e1);
        PKBF(lo1, e2, e3);
        unsigned kh = (unsigned)(c >> 6) * AQP;
        int cl = c & 63;
        unsigned o0 = kh + swzP(r0, cl), o1 = kh + swzP(r0 + 8, cl);
        *(unsigned*)((char*)g_ath + o0) = h0;
        *(unsigned*)((char*)g_ath + o1) = h1;
        *(unsigned*)((char*)g_atl + o0) = lo0;
        *(unsigned*)((char*)g_atl + o1) = lo1;
    }
}

// ---------------------------------------------------------------------------
extern "C" void kernel_launch(void* const* d_in, const int* in_sizes, int n_in,
                              void* d_out, int out_size)
{
    (void)in_sizes; (void)n_in; (void)out_size;
    const float* x   = (const float*)d_in[0];
    const float* adj = (const float*)d_in[1];
    const float* Wq  = (const float*)d_in[2];
    const float* bq  = (const float*)d_in[3];
    const float* Wk  = (const float*)d_in[4];
    const float* bk  = (const float*)d_in[5];
    const float* Wv  = (const float*)d_in[6];
    const float* bv  = (const float*)d_in[7];
    const float* Wo  = (const float*)d_in[8];
    const float* bo  = (const float*)d_in[9];
    float* out = (float*)d_out;

    cudaFuncSetAttribute(gemm_tc_kernel<0>,
                         cudaFuncAttributeMaxDynamicSharedMemorySize, GSMEM);
    cudaFuncSetAttribute(gemm_tc_kernel<1>,
                         cudaFuncAttributeMaxDynamicSharedMemorySize, GSMEM);
    cudaFuncSetAttribute(attn_kernel,
                         cudaFuncAttributeMaxDynamicSharedMemorySize, ASMEM);

    prep_kernel<<<1792, 256>>>(x, adj, Wq, Wk, Wv, Wo);
    gemm_tc_kernel<0><<<dim3(64, 12), 256, GSMEM>>>(bq, bk, bv, nullptr);
    attn_kernel<<<256, 256, ASMEM>>>();
    gemm_tc_kernel<1><<<dim3(64, 4), 256, GSMEM>>>(bo, nullptr, nullptr, out);
}

// round 16
// speedup vs baseline: 1.1959x; 1.1959x over previous
#include <cuda_runtime.h>
#include <cuda_fp16.h>
#include <cuda_bf16.h>
#include <math.h>

#define NTOK 4096
#define QSCALE 0.2550760660737454f   /* (1/sqrt(32)) * log2(e) */
#define NEGL2  -1e30f
#define PLANEB 524288                /* bytes per head-pair fp16 plane: 4096*64*2 */
#define AQP 524288                   /* bytes per K-quarter plane of x/att: 4096*64*2 */
#define WQP 131072                   /* bytes per K-quarter plane of W: 1024*64*2 */

// ---- device scratch (allocation-free rule) ----
// x/att/W bf16 arrays: FOUR K-quarter planes; rows are 128B (64 cols),
// chunk-xor swizzled (chunk ^= row&7) for conflict-free ldmatrix.
static __device__ __align__(1024) __nv_bfloat16 g_xh[NTOK * 256], g_xl[NTOK * 256];
static __device__ __align__(1024) __nv_bfloat16 g_ath[NTOK * 256], g_atl[NTOK * 256];
static __device__ __align__(1024) __nv_bfloat16 g_wth[1024 * 256], g_wtl[1024 * 256];
static __device__ __align__(1024) __half g_q16[NTOK * 256];
static __device__ __align__(1024) __half g_k16[NTOK * 256];
static __device__ __align__(1024) __half g_v16[NTOK * 256];
static __device__ __align__(1024) unsigned g_amask[128 * NTOK];   // [tile32][q]

// ---------------- helpers ----------------
#define PKH(d, lo, hi) \
    asm("cvt.rn.f16x2.f32 %0, %1, %2;" : "=r"(d) : "f"(hi), "f"(lo))
#define PKBF(d, lo, hi) \
    asm("cvt.rn.bf16x2.f32 %0, %1, %2;" : "=r"(d) : "f"(hi), "f"(lo))
#define EX2H2(d, a) \
    asm("ex2.approx.f16x2 %0, %1;" : "=r"(d) : "r"(a))

__device__ __forceinline__ void ldsm4(uint4& r, unsigned addr) {
    asm volatile("ldmatrix.sync.aligned.m8n8.x4.shared.b16 {%0,%1,%2,%3}, [%4];"
                 : "=r"(r.x), "=r"(r.y), "=r"(r.z), "=r"(r.w) : "r"(addr));
}
__device__ __forceinline__ void ldsm4t(uint4& r, unsigned addr) {
    asm volatile("ldmatrix.sync.aligned.m8n8.x4.trans.shared.b16 {%0,%1,%2,%3}, [%4];"
                 : "=r"(r.x), "=r"(r.y), "=r"(r.z), "=r"(r.w) : "r"(addr));
}
__device__ __forceinline__ void mma_f16(
    float& d0, float& d1, float& d2, float& d3,
    unsigned a0, unsigned a1, unsigned a2, unsigned a3,
    unsigned b0, unsigned b1)
{
    asm("mma.sync.aligned.m16n8k16.row.col.f32.f16.f16.f32 "
        "{%0,%1,%2,%3},{%4,%5,%6,%7},{%8,%9},{%0,%1,%2,%3};"
        : "+f"(d0), "+f"(d1), "+f"(d2), "+f"(d3)
        : "r"(a0), "r"(a1), "r"(a2), "r"(a3), "r"(b0), "r"(b1));
}
__device__ __forceinline__ void mma_bf16(
    float& d0, float& d1, float& d2, float& d3,
    unsigned a0, unsigned a1, unsigned a2, unsigned a3,
    unsigned b0, unsigned b1)
{
    asm("mma.sync.aligned.m16n8k16.row.col.f32.bf16.bf16.f32 "
        "{%0,%1,%2,%3},{%4,%5,%6,%7},{%8,%9},{%0,%1,%2,%3};"
        : "+f"(d0), "+f"(d1), "+f"(d2), "+f"(d3)
        : "r"(a0), "r"(a1), "r"(a2), "r"(a3), "r"(b0), "r"(b1));
}
__device__ __forceinline__ void mbar_init(unsigned addr, unsigned cnt) {
    asm volatile("mbarrier.init.shared.b64 [%0], %1;" :: "r"(addr), "r"(cnt) : "memory");
}
__device__ __forceinline__ void mbar_expect(unsigned addr, unsigned tx) {
    asm volatile("mbarrier.arrive.expect_tx.shared.b64 _, [%0], %1;"
                 :: "r"(addr), "r"(tx) : "memory");
}
__device__ __forceinline__ void mbar_wait(unsigned addr, unsigned phase) {
    unsigned done = 0;
    while (!done) {
        asm volatile(
            "{\n .reg .pred p;\n"
            " mbarrier.try_wait.parity.acquire.cta.shared::cta.b64 p, [%1], %2, 0x989680;\n"
            " selp.b32 %0, 1, 0, p;\n}"
            : "=r"(done) : "r"(addr), "r"(phase) : "memory");
    }
}
__device__ __forceinline__ void bulkcp(unsigned dst, const void* src,
                                       unsigned bytes, unsigned mbar) {
    unsigned long long ga;
    asm("cvta.to.global.u64 %0, %1;" : "=l"(ga) : "l"(src));
    asm volatile(
        "cp.async.bulk.shared::cta.global.mbarrier::complete_tx::bytes "
        "[%0], [%1], %2, [%3];"
        :: "r"(dst), "l"(ga), "r"(bytes), "r"(mbar) : "memory");
}

// 128-byte rows (64 x 2B cols), chunk-xor swizzle
__device__ __forceinline__ unsigned swzP(int row, int c) {
    return (unsigned)(row * 128 + ((((c >> 3) ^ (row & 7))) << 4)
                      + ((c & 7) << 1));
}

// ---------------------------------------------------------------------------
// prep: blockIdx < 1024  -> x fp32 -> hi/lo bf16 K-quarter planes
//       1024..1279       -> W transpose -> hi/lo bf16 K-quarter planes
//       1280..1791       -> adj -> bitmask (warp-per-row, coalesced)
// ---------------------------------------------------------------------------
__global__ __launch_bounds__(256) void prep_kernel(
    const float* __restrict__ x, const float* __restrict__ adj,
    const float* __restrict__ Wq, const float* __restrict__ Wk,
    const float* __restrict__ Wv, const float* __restrict__ Wo)
{
    const unsigned b = blockIdx.x;
    if (b < 1024) {
        int idx = b * 256 + threadIdx.x;
        int row = idx >> 6;
        int c4 = (idx & 63) << 2;
        float4 v = *(const float4*)&x[row * 256 + c4];
        unsigned h0, h1, l0, l1;
        PKBF(h0, v.x, v.y);
        PKBF(h1, v.z, v.w);
        float r0 = v.x - __uint_as_float(h0 << 16);
        float r1 = v.y - __uint_as_float(h0 & 0xffff0000u);
        float r2 = v.z - __uint_as_float(h1 << 16);
        float r3 = v.w - __uint_as_float(h1 & 0xffff0000u);
        PKBF(l0, r0, r1);
        PKBF(l1, r2, r3);
        unsigned off = (unsigned)(c4 >> 6) * AQP + swzP(row, c4 & 63);
        uint2 hw = {h0, h1}, lw = {l0, l1};
        *(uint2*)((char*)g_xh + off) = hw;
        *(uint2*)((char*)g_xl + off) = lw;
        return;
    }
    if (b >= 1280) {
        const int q = ((b - 1280) << 3) + (threadIdx.x >> 5);
        const int lane = threadIdx.x & 31;
        const float* row = adj + (size_t)q * NTOK + lane;
#pragma unroll 4
        for (int t = 0; t < 128; t++) {
            float v = row[t << 5];
            unsigned wmask = __ballot_sync(0xffffffffu, v > 0.f);
            if (lane == 0) g_amask[t * NTOK + q] = wmask;
        }
        return;
    }
    __shared__ float sm[32][33];
    const int wb = b - 1024;                    // 0..255
    const int tx = threadIdx.x & 31, ty = threadIdx.x >> 5;
    const int kb = (wb & 7) * 32;
    const int nbi = wb >> 3;
    const int plane = nbi >> 3;
    const float* W = plane == 0 ? Wq : plane == 1 ? Wk : plane == 2 ? Wv : Wo;
    const int nloc = (nbi & 7) * 32;
#pragma unroll
    for (int i = 0; i < 4; i++) {
        int kr = ty * 4 + i;
        sm[kr][tx] = W[(kb + kr) * 256 + nloc + tx];
    }
    __syncthreads();
#pragma unroll
    for (int i = 0; i < 4; i++) {
        int nr = ty * 4 + i;
        float v = sm[tx][nr];
        __nv_bfloat16 h = __float2bfloat16_rn(v);
        __nv_bfloat16 l = __float2bfloat16_rn(v - __bfloat162float(h));
        int grow = plane * 256 + nloc + nr;
        int col = kb + tx;
        unsigned off = (unsigned)(col >> 6) * WQP + swzP(grow, col & 63);
        *(__nv_bfloat16*)((char*)g_wth + off) = h;
        *(__nv_bfloat16*)((char*)g_wtl + off) = l;
    }
}

// ---------------------------------------------------------------------------
// Tensor-core GEMM, M=64 N=64 tiles, K in 4 quarter-stages of 32KB (2 buffered).
// grid (64, NT); 2 CTAs/SM. (unchanged from round 14)
// ---------------------------------------------------------------------------
#define QSTG 32768
#define QA_H 0
#define QA_L 8192
#define QW_H 16384
#define QW_L 24576
#define PBAR 65536
#define GSMEM 65568

template <int MODE>
__global__ __launch_bounds__(256, 2) void gemm_tc_kernel(
    const float* __restrict__ bias0, const float* __restrict__ bias1,
    const float* __restrict__ bias2, float* __restrict__ C)
{
    extern __shared__ char smc[];
    unsigned sb = (unsigned)__cvta_generic_to_shared(smc);

    const int wrow0 = MODE == 0 ? 0 : 768;

    const int tid = threadIdx.x;
    const int lane = tid & 31;
    const int w = tid >> 5;
    const int wm = (w & 3) << 4;
    const int wn = (w >> 2) << 5;
    const int mb = blockIdx.x * 64;
    const int nb = blockIdx.y * 64;
    const int g = lane >> 2, tig = lane & 3;
    const int l7 = lane & 7, lb3 = (lane >> 3) & 1, lb4 = lane >> 4;

    const char* ah = MODE == 0 ? (const char*)g_xh : (const char*)g_ath;
    const char* al = MODE == 0 ? (const char*)g_xl : (const char*)g_atl;
    const int wrow = wrow0 + nb;

    if (tid == 0) {
        mbar_init(sb + PBAR, 1);
        mbar_init(sb + PBAR + 8, 1);
        asm volatile("fence.proxy.async.shared::cta;" ::: "memory");
    }
    __syncthreads();
    if (tid == 0) {
#pragma unroll
        for (int q = 0; q < 2; q++) {
            unsigned bar = sb + PBAR + q * 8;
            unsigned base = sb + q * QSTG;
            mbar_expect(bar, QSTG);
            bulkcp(base + QA_H, ah + (size_t)q * AQP + (size_t)mb * 128, 8192, bar);
            bulkcp(base + QA_L, al + (size_t)q * AQP + (size_t)mb * 128, 8192, bar);
            bulkcp(base + QW_H, (const char*)g_wth + (size_t)q * WQP
                   + (size_t)wrow * 128, 8192, bar);
            bulkcp(base + QW_L, (const char*)g_wtl + (size_t)q * WQP
                   + (size_t)wrow * 128, 8192, bar);
        }
    }

    float acc[4][4];
#pragma unroll
    for (int i = 0; i < 4; i++)
#pragma unroll
        for (int j = 0; j < 4; j++) acc[i][j] = 0.f;

    for (int q = 0; q < 4; q++) {
        const int cur = q & 1;
        mbar_wait(sb + PBAR + cur * 8, (q >> 1) & 1);
        const unsigned base = sb + cur * QSTG;
#pragma unroll
        for (int kc = 0; kc < 4; kc++) {
            uint4 ahf, alf;
            {
                unsigned off = swzP(wm + (lane & 15),
                                    kc * 16 + ((lane >> 4) << 3));
                ldsm4(ahf, base + QA_H + off);
                ldsm4(alf, base + QA_L + off);
            }
            uint4 wh[2], wl[2];
#pragma unroll
            for (int p = 0; p < 2; p++) {
                unsigned off = swzP(wn + 16 * p + lb4 * 8 + l7, kc * 16 + lb3 * 8);
                ldsm4(wh[p], base + QW_H + off);
                ldsm4(wl[p], base + QW_L + off);
            }
#pragma unroll
            for (int nf = 0; nf < 4; nf++) {
                const int p = nf >> 1, s = nf & 1;
                unsigned bh0 = s ? wh[p].z : wh[p].x;
                unsigned bh1 = s ? wh[p].w : wh[p].y;
                unsigned bl0 = s ? wl[p].z : wl[p].x;
                unsigned bl1 = s ? wl[p].w : wl[p].y;
                float* a = acc[nf];
                mma_bf16(a[0], a[1], a[2], a[3],
                         ahf.x, ahf.y, ahf.z, ahf.w, bh0, bh1);
                mma_bf16(a[0], a[1], a[2], a[3],
                         alf.x, alf.y, alf.z, alf.w, bh0, bh1);
                mma_bf16(a[0], a[1], a[2], a[3],
                         ahf.x, ahf.y, ahf.z, ahf.w, bl0, bl1);
            }
        }
        __syncthreads();
        if (tid == 0 && q < 2) {
            const int nq = q + 2;
            unsigned bar = sb + PBAR + cur * 8;
            unsigned bs = sb + cur * QSTG;
            mbar_expect(bar, QSTG);
            bulkcp(bs + QA_H, ah + (size_t)nq * AQP + (size_t)mb * 128, 8192, bar);
            bulkcp(bs + QA_L, al + (size_t)nq * AQP + (size_t)mb * 128, 8192, bar);
            bulkcp(bs + QW_H, (const char*)g_wth + (size_t)nq * WQP
                   + (size_t)wrow * 128, 8192, bar);
            bulkcp(bs + QW_L, (const char*)g_wtl + (size_t)nq * WQP
                   + (size_t)wrow * 128, 8192, bar);
        }
    }

    const int r0 = mb + wm + g;
    if (MODE == 0) {
        const int nwarp = nb + wn;
        const int plane = nwarp >> 8;
        const float* bias = plane == 0 ? bias0 : plane == 1 ? bias1 : bias2;
        __half* dst = plane == 0 ? g_q16 : plane == 1 ? g_k16 : g_v16;
        const float scale = plane == 0 ? QSCALE : 1.0f;
#pragma unroll
        for (int nf = 0; nf < 4; nf++) {
            int c = (nwarp & 255) + tig * 2 + nf * 8;
            float b0 = bias[c], b1 = bias[c + 1];
            float v00 = (acc[nf][0] + b0) * scale;
            float v01 = (acc[nf][1] + b1) * scale;
            float v10 = (acc[nf][2] + b0) * scale;
            float v11 = (acc[nf][3] + b1) * scale;
            unsigned p0, p1;
            PKH(p0, v00, v01);
            PKH(p1, v10, v11);
            size_t pb = (size_t)(c >> 6) * PLANEB;
            *(unsigned*)((char*)dst + pb + swzP(r0, c & 63)) = p0;
            *(unsigned*)((char*)dst + pb + swzP(r0 + 8, c & 63)) = p1;
        }
    } else {
#pragma unroll
        for (int nf = 0; nf < 4; nf++) {
            int c = nb + wn + tig * 2 + nf * 8;
            float b0 = bias0[c], b1 = bias0[c + 1];
            float2 o0 = {acc[nf][0] + b0, acc[nf][1] + b1};
            float2 o1 = {acc[nf][2] + b0, acc[nf][3] + b1};
            *(float2*)&C[(size_t)r0 * 256 + c] = o0;
            *(float2*)&C[(size_t)(r0 + 8) * 256 + c] = o1;
        }
    }
}

// ---------------------------------------------------------------------------
// fp16 flash attention, head-pair planes, 32-key tiles (round-14 structure:
// 2-deep ring, staging after __syncthreads). Mask applied as bitwise AND on
// f16x2 P after ex2 (exactly equivalent; masked lanes were ex2(-1e30)=0).
// grid 256 = 64 q-tiles x 4 planes; block 256 thr / 8 warps, 2 CTAs/SM.
// ---------------------------------------------------------------------------
#define AQ_OFF 0
#define AT_OFF 8192
#define ABUF 8192
#define ABAR 24576                  /* full0, full1, qbar */
#define ASMEM 24608

__device__ __forceinline__ void stage_kv(unsigned sb, int t, int buf,
                                         size_t plane_off) {
    unsigned bar = sb + ABAR + buf * 8;
    unsigned base = sb + AT_OFF + buf * ABUF;
    size_t go = plane_off + (size_t)t * 4096;
    mbar_expect(bar, 8192);
    bulkcp(base,        (const char*)g_k16 + go, 4096, bar);
    bulkcp(base + 4096, (const char*)g_v16 + go, 4096, bar);
}

__global__ __launch_bounds__(256, 2) void attn_kernel()
{
    extern __shared__ char smc[];
    unsigned sb = (unsigned)__cvta_generic_to_shared(smc);

    const int tid = threadIdx.x;
    const int lane = tid & 31;
    const int w = tid >> 5;
    const int hw = w & 1;
    const int qs = (w >> 1) << 4;
    const int hcb = hw << 5;
    const int qtile = blockIdx.x & 63;
    const int hp = blockIdx.x >> 6;
    const int qb = qtile << 6;
    const size_t plane_off = (size_t)hp * PLANEB;
    const int g = lane >> 2, tig = lane & 3;
    const int l7 = lane & 7, lb3 = (lane >> 3) & 1, lb4 = lane >> 4;

    if (tid == 0) {
        mbar_init(sb + ABAR, 1);
        mbar_init(sb + ABAR + 8, 1);
        mbar_init(sb + ABAR + 16, 1);
        asm volatile("fence.proxy.async.shared::cta;" ::: "memory");
    }
    __syncthreads();
    if (tid == 0) {
        unsigned qbar = sb + ABAR + 16;
        mbar_expect(qbar, 8192);
        bulkcp(sb + AQ_OFF, (const char*)g_q16 + plane_off + (size_t)qb * 128,
               8192, qbar);
        stage_kv(sb, 0, 0, plane_off);
        stage_kv(sb, 1, 1, plane_off);
    }

    const unsigned* am = g_amask + qb + qs + g;
    unsigned mw0 = __ldg(am) >> (2 * tig);
    unsigned mw1 = __ldg(am + 8) >> (2 * tig);

    mbar_wait(sb + ABAR + 16, 0);

    unsigned qf[2][4];
#pragma unroll
    for (int kc = 0; kc < 2; kc++) {
        unsigned off = swzP(qs + (lane & 15), hcb + kc * 16 + ((lane >> 4) << 3));
        uint4 r;
        ldsm4(r, sb + AQ_OFF + off);
        qf[kc][0] = r.x; qf[kc][1] = r.y; qf[kc][2] = r.z; qf[kc][3] = r.w;
    }

    float oc[4][4];
#pragma unroll
    for (int i = 0; i < 4; i++)
#pragma unroll
        for (int j = 0; j < 4; j++) oc[i][j] = 0.f;
    float l0 = 0.f, l1 = 0.f;

    for (int t = 0; t < 128; t++) {
        unsigned nw0 = 0, nw1 = 0;
        if (t < 127) {
            nw0 = __ldg(am + (t + 1) * NTOK) >> (2 * tig);
            nw1 = __ldg(am + (t + 1) * NTOK + 8) >> (2 * tig);
        }
        const int cur = t & 1;
        mbar_wait(sb + ABAR + cur * 8, (t >> 1) & 1);
        const unsigned tb = sb + AT_OFF + cur * ABUF;

        uint4 kf[2][2];
#pragma unroll
        for (int kc = 0; kc < 2; kc++)
#pragma unroll
            for (int p = 0; p < 2; p++)
                ldsm4(kf[kc][p], tb + swzP(16 * p + lb4 * 8 + l7,
                                           hcb + kc * 16 + lb3 * 8));

        float sc[4][4];
#pragma unroll
        for (int i = 0; i < 4; i++)
#pragma unroll
            for (int j = 0; j < 4; j++) sc[i][j] = 0.f;
#pragma unroll
        for (int nt = 0; nt < 4; nt++) {
            const int p = nt >> 1, s = nt & 1;
#pragma unroll
            for (int kc = 0; kc < 2; kc++) {
                unsigned b0 = s ? kf[kc][p].z : kf[kc][p].x;
                unsigned b1 = s ? kf[kc][p].w : kf[kc][p].y;
                mma_f16(sc[nt][0], sc[nt][1], sc[nt][2], sc[nt][3],
                        qf[kc][0], qf[kc][1], qf[kc][2], qf[kc][3], b0, b1);
            }
        }

        // ---- exp (fixed shift) then bitwise mask; l accumulation ----
        unsigned pA[4][2];
        __half2 lh0 = __float2half2_rn(0.f), lh1 = __float2half2_rn(0.f);
#pragma unroll
        for (int nt = 0; nt < 4; nt++) {
            unsigned b0 = (mw0 >> (nt * 8)) & 3u;
            unsigned b1 = (mw1 >> (nt * 8)) & 3u;
            unsigned m0 = ((b0 & 1u) ? 0x0000FFFFu : 0u) | ((b0 & 2u) ? 0xFFFF0000u : 0u);
            unsigned m1 = ((b1 & 1u) ? 0x0000FFFFu : 0u) | ((b1 & 2u) ? 0xFFFF0000u : 0u);
            unsigned h0, h1;
            PKH(h0, sc[nt][0], sc[nt][1]);
            PKH(h1, sc[nt][2], sc[nt][3]);
            EX2H2(pA[nt][0], h0);
            EX2H2(pA[nt][1], h1);
            pA[nt][0] &= m0;
            pA[nt][1] &= m1;
            lh0 = __hadd2(lh0, *(__half2*)&pA[nt][0]);
            lh1 = __hadd2(lh1, *(__half2*)&pA[nt][1]);
        }
        {
            float2 f0 = __half22float2(lh0);
            float2 f1 = __half22float2(lh1);
            l0 += f0.x + f0.y;
            l1 += f1.x + f1.y;
        }

        uint4 vf[2][2];
#pragma unroll
        for (int kc = 0; kc < 2; kc++)
#pragma unroll
            for (int p = 0; p < 2; p++)
                ldsm4t(vf[kc][p], tb + 4096 + swzP(kc * 16 + lb3 * 8 + l7,
                                                   hcb + p * 16 + lb4 * 8));

#pragma unroll
        for (int nt = 0; nt < 4; nt++) {
            const int p = nt >> 1, s = nt & 1;
#pragma unroll
            for (int kc = 0; kc < 2; kc++) {
                unsigned b0 = s ? vf[kc][p].z : vf[kc][p].x;
                unsigned b1 = s ? vf[kc][p].w : vf[kc][p].y;
                mma_f16(oc[nt][0], oc[nt][1], oc[nt][2], oc[nt][3],
                        pA[2 * kc][0], pA[2 * kc][1],
                        pA[2 * kc + 1][0], pA[2 * kc + 1][1], b0, b1);
            }
        }

        __syncthreads();
        if (tid == 0 && t < 126) stage_kv(sb, t + 2, cur, plane_off);
        mw0 = nw0; mw1 = nw1;
    }

    l0 += __shfl_xor_sync(0xffffffffu, l0, 1);
    l0 += __shfl_xor_sync(0xffffffffu, l0, 2);
    l1 += __shfl_xor_sync(0xffffffffu, l1, 1);
    l1 += __shfl_xor_sync(0xffffffffu, l1, 2);
    float inv0 = 1.f / l0, inv1 = 1.f / l1;

    // epilogue -> hi/lo bf16 in K-quarter-plane layout for the output gemm
    const int r0 = qb + qs + g;
    const int colb = ((hp << 1) + hw) * 32 + tig * 2;
#pragma unroll
    for (int nt = 0; nt < 4; nt++) {
        int c = colb + nt * 8;
        float v00 = oc[nt][0] * inv0, v01 = oc[nt][1] * inv0;
        float v10 = oc[nt][2] * inv1, v11 = oc[nt][3] * inv1;
        unsigned h0, h1, lo0, lo1;
        PKBF(h0, v00, v01);
        PKBF(h1, v10, v11);
        float e0 = v00 - __uint_as_float(h0 << 16);
        float e1 = v01 - __uint_as_float(h0 & 0xffff0000u);
        float e2 = v10 - __uint_as_float(h1 << 16);
        float e3 = v11 - __uint_as_float(h1 & 0xffff0000u);
        PKBF(lo0, e0, e1);
        PKBF(lo1, e2, e3);
        unsigned kh = (unsigned)(c >> 6) * AQP;
        int cl = c & 63;
        unsigned o0 = kh + swzP(r0, cl), o1 = kh + swzP(r0 + 8, cl);
        *(unsigned*)((char*)g_ath + o0) = h0;
        *(unsigned*)((char*)g_ath + o1) = h1;
        *(unsigned*)((char*)g_atl + o0) = lo0;
        *(unsigned*)((char*)g_atl + o1) = lo1;
    }
}

// ---------------------------------------------------------------------------
extern "C" void kernel_launch(void* const* d_in, const int* in_sizes, int n_in,
                              void* d_out, int out_size)
{
    (void)in_sizes; (void)n_in; (void)out_size;
    const float* x   = (const float*)d_in[0];
    const float* adj = (const float*)d_in[1];
    const float* Wq  = (const float*)d_in[2];
    const float* bq  = (const float*)d_in[3];
    const float* Wk  = (const float*)d_in[4];
    const float* bk  = (const float*)d_in[5];
    const float* Wv  = (const float*)d_in[6];
    const float* bv  = (const float*)d_in[7];
    const float* Wo  = (const float*)d_in[8];
    const float* bo  = (const float*)d_in[9];
    float* out = (float*)d_out;

    cudaFuncSetAttribute(gemm_tc_kernel<0>,
                         cudaFuncAttributeMaxDynamicSharedMemorySize, GSMEM);
    cudaFuncSetAttribute(gemm_tc_kernel<1>,
                         cudaFuncAttributeMaxDynamicSharedMemorySize, GSMEM);
    cudaFuncSetAttribute(attn_kernel,
                         cudaFuncAttributeMaxDynamicSharedMemorySize, ASMEM);

    prep_kernel<<<1792, 256>>>(x, adj, Wq, Wk, Wv, Wo);
    gemm_tc_kernel<0><<<dim3(64, 12), 256, GSMEM>>>(bq, bk, bv, nullptr);
    attn_kernel<<<256, 256, ASMEM>>>();
    gemm_tc_kernel<1><<<dim3(64, 4), 256, GSMEM>>>(bo, nullptr, nullptr, out);
}

// round 17
// speedup vs baseline: 1.2749x; 1.0660x over previous
#include <cuda_runtime.h>
#include <cuda_fp16.h>
#include <cuda_bf16.h>
#include <math.h>

#define NTOK 4096
#define QSCALE 0.2550760660737454f   /* (1/sqrt(32)) * log2(e) */
#define NEGL2  -1e30f
#define PLANEB 524288                /* bytes per head-pair fp16 plane: 4096*64*2 */
#define AQP 524288                   /* bytes per K-quarter plane of x/att: 4096*64*2 */
#define WQP 131072                   /* bytes per K-quarter plane of W: 1024*64*2 */

// ---- device scratch (allocation-free rule) ----
// x/att/W bf16 arrays: FOUR K-quarter planes; rows are 128B (64 cols),
// chunk-xor swizzled (chunk ^= row&7) for conflict-free ldmatrix.
static __device__ __align__(1024) __nv_bfloat16 g_xh[NTOK * 256], g_xl[NTOK * 256];
static __device__ __align__(1024) __nv_bfloat16 g_ath[NTOK * 256], g_atl[NTOK * 256];
static __device__ __align__(1024) __nv_bfloat16 g_wth[1024 * 256], g_wtl[1024 * 256];
static __device__ __align__(1024) __half g_q16[NTOK * 256];
static __device__ __align__(1024) __half g_k16[NTOK * 256];
static __device__ __align__(1024) __half g_v16[NTOK * 256];
static __device__ __align__(1024) unsigned g_amask[128 * NTOK];   // [tile32][q]

// ---------------- helpers ----------------
#define PKH(d, lo, hi) \
    asm("cvt.rn.f16x2.f32 %0, %1, %2;" : "=r"(d) : "f"(hi), "f"(lo))
#define PKBF(d, lo, hi) \
    asm("cvt.rn.bf16x2.f32 %0, %1, %2;" : "=r"(d) : "f"(hi), "f"(lo))
#define EX2H2(d, a) \
    asm("ex2.approx.f16x2 %0, %1;" : "=r"(d) : "r"(a))

__device__ __forceinline__ void ldsm4(uint4& r, unsigned addr) {
    asm volatile("ldmatrix.sync.aligned.m8n8.x4.shared.b16 {%0,%1,%2,%3}, [%4];"
                 : "=r"(r.x), "=r"(r.y), "=r"(r.z), "=r"(r.w) : "r"(addr));
}
__device__ __forceinline__ void ldsm4t(uint4& r, unsigned addr) {
    asm volatile("ldmatrix.sync.aligned.m8n8.x4.trans.shared.b16 {%0,%1,%2,%3}, [%4];"
                 : "=r"(r.x), "=r"(r.y), "=r"(r.z), "=r"(r.w) : "r"(addr));
}
__device__ __forceinline__ void mma_f16(
    float& d0, float& d1, float& d2, float& d3,
    unsigned a0, unsigned a1, unsigned a2, unsigned a3,
    unsigned b0, unsigned b1)
{
    asm("mma.sync.aligned.m16n8k16.row.col.f32.f16.f16.f32 "
        "{%0,%1,%2,%3},{%4,%5,%6,%7},{%8,%9},{%0,%1,%2,%3};"
        : "+f"(d0), "+f"(d1), "+f"(d2), "+f"(d3)
        : "r"(a0), "r"(a1), "r"(a2), "r"(a3), "r"(b0), "r"(b1));
}
__device__ __forceinline__ void mma_bf16(
    float& d0, float& d1, float& d2, float& d3,
    unsigned a0, unsigned a1, unsigned a2, unsigned a3,
    unsigned b0, unsigned b1)
{
    asm("mma.sync.aligned.m16n8k16.row.col.f32.bf16.bf16.f32 "
        "{%0,%1,%2,%3},{%4,%5,%6,%7},{%8,%9},{%0,%1,%2,%3};"
        : "+f"(d0), "+f"(d1), "+f"(d2), "+f"(d3)
        : "r"(a0), "r"(a1), "r"(a2), "r"(a3), "r"(b0), "r"(b1));
}
__device__ __forceinline__ void mbar_init(unsigned addr, unsigned cnt) {
    asm volatile("mbarrier.init.shared.b64 [%0], %1;" :: "r"(addr), "r"(cnt) : "memory");
}
__device__ __forceinline__ void mbar_expect(unsigned addr, unsigned tx) {
    asm volatile("mbarrier.arrive.expect_tx.shared.b64 _, [%0], %1;"
                 :: "r"(addr), "r"(tx) : "memory");
}
__device__ __forceinline__ void mbar_wait(unsigned addr, unsigned phase) {
    unsigned done = 0;
    while (!done) {
        asm volatile(
            "{\n .reg .pred p;\n"
            " mbarrier.try_wait.parity.acquire.cta.shared::cta.b64 p, [%1], %2, 0x989680;\n"
            " selp.b32 %0, 1, 0, p;\n}"
            : "=r"(done) : "r"(addr), "r"(phase) : "memory");
    }
}
__device__ __forceinline__ void bulkcp(unsigned dst, const void* src,
                                       unsigned bytes, unsigned mbar) {
    unsigned long long ga;
    asm("cvta.to.global.u64 %0, %1;" : "=l"(ga) : "l"(src));
    asm volatile(
        "cp.async.bulk.shared::cta.global.mbarrier::complete_tx::bytes "
        "[%0], [%1], %2, [%3];"
        :: "r"(dst), "l"(ga), "r"(bytes), "r"(mbar) : "memory");
}

// 128-byte rows (64 x 2B cols), chunk-xor swizzle
__device__ __forceinline__ unsigned swzP(int row, int c) {
    return (unsigned)(row * 128 + ((((c >> 3) ^ (row & 7))) << 4)
                      + ((c & 7) << 1));
}

// ---------------------------------------------------------------------------
// prep: blockIdx < 1024  -> x fp32 -> hi/lo bf16 K-quarter planes
//       1024..1279       -> W transpose -> hi/lo bf16 K-quarter planes
//       1280..1791       -> adj -> bitmask (warp-per-row, coalesced)
// ---------------------------------------------------------------------------
__global__ __launch_bounds__(256) void prep_kernel(
    const float* __restrict__ x, const float* __restrict__ adj,
    const float* __restrict__ Wq, const float* __restrict__ Wk,
    const float* __restrict__ Wv, const float* __restrict__ Wo)
{
    const unsigned b = blockIdx.x;
    if (b < 1024) {
        int idx = b * 256 + threadIdx.x;
        int row = idx >> 6;
        int c4 = (idx & 63) << 2;
        float4 v = *(const float4*)&x[row * 256 + c4];
        unsigned h0, h1, l0, l1;
        PKBF(h0, v.x, v.y);
        PKBF(h1, v.z, v.w);
        float r0 = v.x - __uint_as_float(h0 << 16);
        float r1 = v.y - __uint_as_float(h0 & 0xffff0000u);
        float r2 = v.z - __uint_as_float(h1 << 16);
        float r3 = v.w - __uint_as_float(h1 & 0xffff0000u);
        PKBF(l0, r0, r1);
        PKBF(l1, r2, r3);
        unsigned off = (unsigned)(c4 >> 6) * AQP + swzP(row, c4 & 63);
        uint2 hw = {h0, h1}, lw = {l0, l1};
        *(uint2*)((char*)g_xh + off) = hw;
        *(uint2*)((char*)g_xl + off) = lw;
        return;
    }
    if (b >= 1280) {
        const int q = ((b - 1280) << 3) + (threadIdx.x >> 5);
        const int lane = threadIdx.x & 31;
        const float* row = adj + (size_t)q * NTOK + lane;
#pragma unroll 4
        for (int t = 0; t < 128; t++) {
            float v = row[t << 5];
            unsigned wmask = __ballot_sync(0xffffffffu, v > 0.f);
            if (lane == 0) g_amask[t * NTOK + q] = wmask;
        }
        return;
    }
    __shared__ float sm[32][33];
    const int wb = b - 1024;                    // 0..255
    const int tx = threadIdx.x & 31, ty = threadIdx.x >> 5;
    const int kb = (wb & 7) * 32;
    const int nbi = wb >> 3;
    const int plane = nbi >> 3;
    const float* W = plane == 0 ? Wq : plane == 1 ? Wk : plane == 2 ? Wv : Wo;
    const int nloc = (nbi & 7) * 32;
#pragma unroll
    for (int i = 0; i < 4; i++) {
        int kr = ty * 4 + i;
        sm[kr][tx] = W[(kb + kr) * 256 + nloc + tx];
    }
    __syncthreads();
#pragma unroll
    for (int i = 0; i < 4; i++) {
        int nr = ty * 4 + i;
        float v = sm[tx][nr];
        __nv_bfloat16 h = __float2bfloat16_rn(v);
        __nv_bfloat16 l = __float2bfloat16_rn(v - __bfloat162float(h));
        int grow = plane * 256 + nloc + nr;
        int col = kb + tx;
        unsigned off = (unsigned)(col >> 6) * WQP + swzP(grow, col & 63);
        *(__nv_bfloat16*)((char*)g_wth + off) = h;
        *(__nv_bfloat16*)((char*)g_wtl + off) = l;
    }
}

// ---------------------------------------------------------------------------
// Tensor-core GEMM, M=64 N=64 tiles, K in 4 quarter-stages of 32KB (2 buffered).
// grid (64, NT); 2 CTAs/SM. (unchanged from round 14)
// ---------------------------------------------------------------------------
#define QSTG 32768
#define QA_H 0
#define QA_L 8192
#define QW_H 16384
#define QW_L 24576
#define PBAR 65536
#define GSMEM 65568

template <int MODE>
__global__ __launch_bounds__(256, 2) void gemm_tc_kernel(
    const float* __restrict__ bias0, const float* __restrict__ bias1,
    const float* __restrict__ bias2, float* __restrict__ C)
{
    extern __shared__ char smc[];
    unsigned sb = (unsigned)__cvta_generic_to_shared(smc);

    const int wrow0 = MODE == 0 ? 0 : 768;

    const int tid = threadIdx.x;
    const int lane = tid & 31;
    const int w = tid >> 5;
    const int wm = (w & 3) << 4;
    const int wn = (w >> 2) << 5;
    const int mb = blockIdx.x * 64;
    const int nb = blockIdx.y * 64;
    const int g = lane >> 2, tig = lane & 3;
    const int l7 = lane & 7, lb3 = (lane >> 3) & 1, lb4 = lane >> 4;

    const char* ah = MODE == 0 ? (const char*)g_xh : (const char*)g_ath;
    const char* al = MODE == 0 ? (const char*)g_xl : (const char*)g_atl;
    const int wrow = wrow0 + nb;

    if (tid == 0) {
        mbar_init(sb + PBAR, 1);
        mbar_init(sb + PBAR + 8, 1);
        asm volatile("fence.proxy.async.shared::cta;" ::: "memory");
    }
    __syncthreads();
    if (tid == 0) {
#pragma unroll
        for (int q = 0; q < 2; q++) {
            unsigned bar = sb + PBAR + q * 8;
            unsigned base = sb + q * QSTG;
            mbar_expect(bar, QSTG);
            bulkcp(base + QA_H, ah + (size_t)q * AQP + (size_t)mb * 128, 8192, bar);
            bulkcp(base + QA_L, al + (size_t)q * AQP + (size_t)mb * 128, 8192, bar);
            bulkcp(base + QW_H, (const char*)g_wth + (size_t)q * WQP
                   + (size_t)wrow * 128, 8192, bar);
            bulkcp(base + QW_L, (const char*)g_wtl + (size_t)q * WQP
                   + (size_t)wrow * 128, 8192, bar);
        }
    }

    float acc[4][4];
#pragma unroll
    for (int i = 0; i < 4; i++)
#pragma unroll
        for (int j = 0; j < 4; j++) acc[i][j] = 0.f;

    for (int q = 0; q < 4; q++) {
        const int cur = q & 1;
        mbar_wait(sb + PBAR + cur * 8, (q >> 1) & 1);
        const unsigned base = sb + cur * QSTG;
#pragma unroll
        for (int kc = 0; kc < 4; kc++) {
            uint4 ahf, alf;
            {
                unsigned off = swzP(wm + (lane & 15),
                                    kc * 16 + ((lane >> 4) << 3));
                ldsm4(ahf, base + QA_H + off);
                ldsm4(alf, base + QA_L + off);
            }
            uint4 wh[2], wl[2];
#pragma unroll
            for (int p = 0; p < 2; p++) {
                unsigned off = swzP(wn + 16 * p + lb4 * 8 + l7, kc * 16 + lb3 * 8);
                ldsm4(wh[p], base + QW_H + off);
                ldsm4(wl[p], base + QW_L + off);
            }
#pragma unroll
            for (int nf = 0; nf < 4; nf++) {
                const int p = nf >> 1, s = nf & 1;
                unsigned bh0 = s ? wh[p].z : wh[p].x;
                unsigned bh1 = s ? wh[p].w : wh[p].y;
                unsigned bl0 = s ? wl[p].z : wl[p].x;
                unsigned bl1 = s ? wl[p].w : wl[p].y;
                float* a = acc[nf];
                mma_bf16(a[0], a[1], a[2], a[3],
                         ahf.x, ahf.y, ahf.z, ahf.w, bh0, bh1);
                mma_bf16(a[0], a[1], a[2], a[3],
                         alf.x, alf.y, alf.z, alf.w, bh0, bh1);
                mma_bf16(a[0], a[1], a[2], a[3],
                         ahf.x, ahf.y, ahf.z, ahf.w, bl0, bl1);
            }
        }
        __syncthreads();
        if (tid == 0 && q < 2) {
            const int nq = q + 2;
            unsigned bar = sb + PBAR + cur * 8;
            unsigned bs = sb + cur * QSTG;
            mbar_expect(bar, QSTG);
            bulkcp(bs + QA_H, ah + (size_t)nq * AQP + (size_t)mb * 128, 8192, bar);
            bulkcp(bs + QA_L, al + (size_t)nq * AQP + (size_t)mb * 128, 8192, bar);
            bulkcp(bs + QW_H, (const char*)g_wth + (size_t)nq * WQP
                   + (size_t)wrow * 128, 8192, bar);
            bulkcp(bs + QW_L, (const char*)g_wtl + (size_t)nq * WQP
                   + (size_t)wrow * 128, 8192, bar);
        }
    }

    const int r0 = mb + wm + g;
    if (MODE == 0) {
        const int nwarp = nb + wn;
        const int plane = nwarp >> 8;
        const float* bias = plane == 0 ? bias0 : plane == 1 ? bias1 : bias2;
        __half* dst = plane == 0 ? g_q16 : plane == 1 ? g_k16 : g_v16;
        const float scale = plane == 0 ? QSCALE : 1.0f;
#pragma unroll
        for (int nf = 0; nf < 4; nf++) {
            int c = (nwarp & 255) + tig * 2 + nf * 8;
            float b0 = bias[c], b1 = bias[c + 1];
            float v00 = (acc[nf][0] + b0) * scale;
            float v01 = (acc[nf][1] + b1) * scale;
            float v10 = (acc[nf][2] + b0) * scale;
            float v11 = (acc[nf][3] + b1) * scale;
            unsigned p0, p1;
            PKH(p0, v00, v01);
            PKH(p1, v10, v11);
            size_t pb = (size_t)(c >> 6) * PLANEB;
            *(unsigned*)((char*)dst + pb + swzP(r0, c & 63)) = p0;
            *(unsigned*)((char*)dst + pb + swzP(r0 + 8, c & 63)) = p1;
        }
    } else {
#pragma unroll
        for (int nf = 0; nf < 4; nf++) {
            int c = nb + wn + tig * 2 + nf * 8;
            float b0 = bias0[c], b1 = bias0[c + 1];
            float2 o0 = {acc[nf][0] + b0, acc[nf][1] + b1};
            float2 o1 = {acc[nf][2] + b0, acc[nf][3] + b1};
            *(float2*)&C[(size_t)r0 * 256 + c] = o0;
            *(float2*)&C[(size_t)(r0 + 8) * 256 + c] = o1;
        }
    }
}

// ---------------------------------------------------------------------------
// fp16 flash attention, head-pair planes, 32-key tiles.
// Round-14 structure (fp32-select mask, staging after __syncthreads) with a
// 4-deep KV ring: at end of iteration t stage tile t+3 into buffer (t+3)&3,
// which was last consumed at iteration t-1 -> 3 iterations of TMA slack.
// grid 256 = 64 q-tiles x 4 planes; block 256 thr / 8 warps, 2 CTAs/SM.
// ---------------------------------------------------------------------------
#define AQ_OFF 0
#define AT_OFF 8192
#define ABUF 8192
#define ABAR 40960                  /* full0..full3, qbar */
#define ASMEM 41008

__device__ __forceinline__ void stage_kv(unsigned sb, int t, size_t plane_off) {
    const int buf = t & 3;
    unsigned bar = sb + ABAR + buf * 8;
    unsigned base = sb + AT_OFF + buf * ABUF;
    size_t go = plane_off + (size_t)t * 4096;
    mbar_expect(bar, 8192);
    bulkcp(base,        (const char*)g_k16 + go, 4096, bar);
    bulkcp(base + 4096, (const char*)g_v16 + go, 4096, bar);
}

__global__ __launch_bounds__(256, 2) void attn_kernel()
{
    extern __shared__ char smc[];
    unsigned sb = (unsigned)__cvta_generic_to_shared(smc);

    const int tid = threadIdx.x;
    const int lane = tid & 31;
    const int w = tid >> 5;
    const int hw = w & 1;
    const int qs = (w >> 1) << 4;
    const int hcb = hw << 5;
    const int qtile = blockIdx.x & 63;
    const int hp = blockIdx.x >> 6;
    const int qb = qtile << 6;
    const size_t plane_off = (size_t)hp * PLANEB;
    const int g = lane >> 2, tig = lane & 3;
    const int l7 = lane & 7, lb3 = (lane >> 3) & 1, lb4 = lane >> 4;

    if (tid == 0) {
        mbar_init(sb + ABAR, 1);
        mbar_init(sb + ABAR + 8, 1);
        mbar_init(sb + ABAR + 16, 1);
        mbar_init(sb + ABAR + 24, 1);
        mbar_init(sb + ABAR + 32, 1);   // q
        asm volatile("fence.proxy.async.shared::cta;" ::: "memory");
    }
    __syncthreads();
    if (tid == 0) {
        unsigned qbar = sb + ABAR + 32;
        mbar_expect(qbar, 8192);
        bulkcp(sb + AQ_OFF, (const char*)g_q16 + plane_off + (size_t)qb * 128,
               8192, qbar);
        stage_kv(sb, 0, plane_off);
        stage_kv(sb, 1, plane_off);
        stage_kv(sb, 2, plane_off);
    }

    const unsigned* am = g_amask + qb + qs + g;
    unsigned mw0 = __ldg(am);
    unsigned mw1 = __ldg(am + 8);

    mbar_wait(sb + ABAR + 32, 0);

    unsigned qf[2][4];
#pragma unroll
    for (int kc = 0; kc < 2; kc++) {
        unsigned off = swzP(qs + (lane & 15), hcb + kc * 16 + ((lane >> 4) << 3));
        uint4 r;
        ldsm4(r, sb + AQ_OFF + off);
        qf[kc][0] = r.x; qf[kc][1] = r.y; qf[kc][2] = r.z; qf[kc][3] = r.w;
    }

    float oc[4][4];
#pragma unroll
    for (int i = 0; i < 4; i++)
#pragma unroll
        for (int j = 0; j < 4; j++) oc[i][j] = 0.f;
    float l0 = 0.f, l1 = 0.f;

    for (int t = 0; t < 128; t++) {
        unsigned nw0 = 0, nw1 = 0;
        if (t < 127) {
            nw0 = __ldg(am + (t + 1) * NTOK);
            nw1 = __ldg(am + (t + 1) * NTOK + 8);
        }
        mbar_wait(sb + ABAR + (t & 3) * 8, (t >> 2) & 1);
        const unsigned tb = sb + AT_OFF + (t & 3) * ABUF;

        uint4 kf[2][2];
#pragma unroll
        for (int kc = 0; kc < 2; kc++)
#pragma unroll
            for (int p = 0; p < 2; p++)
                ldsm4(kf[kc][p], tb + swzP(16 * p + lb4 * 8 + l7,
                                           hcb + kc * 16 + lb3 * 8));

        float sc[4][4];
#pragma unroll
        for (int i = 0; i < 4; i++)
#pragma unroll
            for (int j = 0; j < 4; j++) sc[i][j] = 0.f;
#pragma unroll
        for (int nt = 0; nt < 4; nt++) {
            const int p = nt >> 1, s = nt & 1;
#pragma unroll
            for (int kc = 0; kc < 2; kc++) {
                unsigned b0 = s ? kf[kc][p].z : kf[kc][p].x;
                unsigned b1 = s ? kf[kc][p].w : kf[kc][p].y;
                mma_f16(sc[nt][0], sc[nt][1], sc[nt][2], sc[nt][3],
                        qf[kc][0], qf[kc][1], qf[kc][2], qf[kc][3], b0, b1);
            }
        }

        // ---- mask (fp32 selects) + exp (fixed shift) + l accumulation ----
        unsigned pA[4][2];
        __half2 lh0 = __float2half2_rn(0.f), lh1 = __float2half2_rn(0.f);
#pragma unroll
        for (int nt = 0; nt < 4; nt++) {
            int j0 = nt * 8 + 2 * tig;
            float s0 = ((mw0 >> j0) & 1) ? sc[nt][0] : NEGL2;
            float s1 = ((mw0 >> (j0 + 1)) & 1) ? sc[nt][1] : NEGL2;
            float s2 = ((mw1 >> j0) & 1) ? sc[nt][2] : NEGL2;
            float s3 = ((mw1 >> (j0 + 1)) & 1) ? sc[nt][3] : NEGL2;
            unsigned h0, h1;
            PKH(h0, s0, s1);
            PKH(h1, s2, s3);
            EX2H2(pA[nt][0], h0);
            EX2H2(pA[nt][1], h1);
            lh0 = __hadd2(lh0, *(__half2*)&pA[nt][0]);
            lh1 = __hadd2(lh1, *(__half2*)&pA[nt][1]);
        }
        {
            float2 f0 = __half22float2(lh0);
            float2 f1 = __half22float2(lh1);
            l0 += f0.x + f0.y;
            l1 += f1.x + f1.y;
        }

        uint4 vf[2][2];
#pragma unroll
        for (int kc = 0; kc < 2; kc++)
#pragma unroll
            for (int p = 0; p < 2; p++)
                ldsm4t(vf[kc][p], tb + 4096 + swzP(kc * 16 + lb3 * 8 + l7,
                                                   hcb + p * 16 + lb4 * 8));

#pragma unroll
        for (int nt = 0; nt < 4; nt++) {
            const int p = nt >> 1, s = nt & 1;
#pragma unroll
            for (int kc = 0; kc < 2; kc++) {
                unsigned b0 = s ? vf[kc][p].z : vf[kc][p].x;
                unsigned b1 = s ? vf[kc][p].w : vf[kc][p].y;
                mma_f16(oc[nt][0], oc[nt][1], oc[nt][2], oc[nt][3],
                        pA[2 * kc][0], pA[2 * kc][1],
                        pA[2 * kc + 1][0], pA[2 * kc + 1][1], b0, b1);
            }
        }

        __syncthreads();
        if (tid == 0 && t < 125) stage_kv(sb, t + 3, plane_off);
        mw0 = nw0; mw1 = nw1;
    }

    l0 += __shfl_xor_sync(0xffffffffu, l0, 1);
    l0 += __shfl_xor_sync(0xffffffffu, l0, 2);
    l1 += __shfl_xor_sync(0xffffffffu, l1, 1);
    l1 += __shfl_xor_sync(0xffffffffu, l1, 2);
    float inv0 = 1.f / l0, inv1 = 1.f / l1;

    // epilogue -> hi/lo bf16 in K-quarter-plane layout for the output gemm
    const int r0 = qb + qs + g;
    const int colb = ((hp << 1) + hw) * 32 + tig * 2;
#pragma unroll
    for (int nt = 0; nt < 4; nt++) {
        int c = colb + nt * 8;
        float v00 = oc[nt][0] * inv0, v01 = oc[nt][1] * inv0;
        float v10 = oc[nt][2] * inv1, v11 = oc[nt][3] * inv1;
        unsigned h0, h1, lo0, lo1;
        PKBF(h0, v00, v01);
        PKBF(h1, v10, v11);
        float e0 = v00 - __uint_as_float(h0 << 16);
        float e1 = v01 - __uint_as_float(h0 & 0xffff0000u);
        float e2 = v10 - __uint_as_float(h1 << 16);
        float e3 = v11 - __uint_as_float(h1 & 0xffff0000u);
        PKBF(lo0, e0, e1);
        PKBF(lo1, e2, e3);
        unsigned kh = (unsigned)(c >> 6) * AQP;
        int cl = c & 63;
        unsigned o0 = kh + swzP(r0, cl), o1 = kh + swzP(r0 + 8, cl);
        *(unsigned*)((char*)g_ath + o0) = h0;
        *(unsigned*)((char*)g_ath + o1) = h1;
        *(unsigned*)((char*)g_atl + o0) = lo0;
        *(unsigned*)((char*)g_atl + o1) = lo1;
    }
}

// ---------------------------------------------------------------------------
extern "C" void kernel_launch(void* const* d_in, const int* in_sizes, int n_in,
                              void* d_out, int out_size)
{
    (void)in_sizes; (void)n_in; (void)out_size;
    const float* x   = (const float*)d_in[0];
    const float* adj = (const float*)d_in[1];
    const float* Wq  = (const float*)d_in[2];
    const float* bq  = (const float*)d_in[3];
    const float* Wk  = (const float*)d_in[4];
    const float* bk  = (const float*)d_in[5];
    const float* Wv  = (const float*)d_in[6];
    const float* bv  = (const float*)d_in[7];
    const float* Wo  = (const float*)d_in[8];
    const float* bo  = (const float*)d_in[9];
    float* out = (float*)d_out;

    cudaFuncSetAttribute(gemm_tc_kernel<0>,
                         cudaFuncAttributeMaxDynamicSharedMemorySize, GSMEM);
    cudaFuncSetAttribute(gemm_tc_kernel<1>,
                         cudaFuncAttributeMaxDynamicSharedMemorySize, GSMEM);
    cudaFuncSetAttribute(attn_kernel,
                         cudaFuncAttributeMaxDynamicSharedMemorySize, ASMEM);

    prep_kernel<<<1792, 256>>>(x, adj, Wq, Wk, Wv, Wo);
    gemm_tc_kernel<0><<<dim3(64, 12), 256, GSMEM>>>(bq, bk, bv, nullptr);
    attn_kernel<<<256, 256, ASMEM>>>();
    gemm_tc_kernel<1><<<dim3(64, 4), 256, GSMEM>>>(bo, nullptr, nullptr, out);
}